// round 1
// baseline (speedup 1.0000x reference)
#include <cuda_runtime.h>
#include <math.h>

#define B 32
#define C 512
#define Q 128
#define D 768
#define OD (4*D)   // 3072

#define NEGBIG (-1e30f)

// ---------------- scratch (no allocations allowed) ----------------
__device__ float g_sim[(size_t)B*C*Q];     // sim, later overwritten with dist
__device__ float g_a[B*C];                 // c . w1
__device__ float g_bq[B*Q];                // q . w2
__device__ float g_smax[B*C];              // max over q of raw sim
__device__ float g_colmax[B*Q];
__device__ float g_colsum[B*Q];
__device__ float g_cdw[B*C];               // c_dash softmax weights
__device__ float g_cdash[B*D];             // c_dash vector per batch

// ---------------- K1: row dots (c.w1, q.w2) ----------------
__global__ void k_rowdots(const float* __restrict__ cont,
                          const float* __restrict__ ques,
                          const float* __restrict__ SW) {
    int warp = (blockIdx.x * blockDim.x + threadIdx.x) >> 5;
    int lane = threadIdx.x & 31;
    const int NC = B * C;
    float acc = 0.f;
    if (warp < NC) {
        const float* row = cont + (size_t)warp * D;
        const float* w = SW;  // w1
        #pragma unroll 4
        for (int d = lane; d < D; d += 32) acc += row[d] * w[d];
        #pragma unroll
        for (int o = 16; o; o >>= 1) acc += __shfl_xor_sync(0xffffffffu, acc, o);
        if (!lane) g_a[warp] = acc;
    } else if (warp < NC + B * Q) {
        int r = warp - NC;
        const float* row = ques + (size_t)r * D;
        const float* w = SW + D;  // w2
        #pragma unroll 4
        for (int d = lane; d < D; d += 32) acc += row[d] * w[d];
        #pragma unroll
        for (int o = 16; o; o >>= 1) acc += __shfl_xor_sync(0xffffffffu, acc, o);
        if (!lane) g_bq[r] = acc;
    }
}

// ---------------- K2: sim GEMM: sim[b,c,q] = a[c] + bq[q] + (cont*w3).ques ----------------
// 64x64 tile, 256 threads, 4x4 microtile, BK=16
__global__ __launch_bounds__(256) void k_sim(const float* __restrict__ cont,
                                             const float* __restrict__ ques,
                                             const float* __restrict__ SW) {
    __shared__ float As[16][64];  // [k][c]
    __shared__ float Bs[16][64];  // [k][q]
    const int b  = blockIdx.z;
    const int c0 = blockIdx.x * 64;
    const int q0 = blockIdx.y * 64;
    const float* A  = cont + ((size_t)b * C + c0) * D;
    const float* Bq = ques + ((size_t)b * Q + q0) * D;
    const float* w3 = SW + 2 * D;
    const int t = threadIdx.x;
    const int lr = t >> 2;          // 0..63  load row
    const int lk = (t & 3) * 4;     // 0,4,8,12
    const int tm = (t >> 4) * 4;    // row base (c)
    const int tn = (t & 15) * 4;    // col base (q)

    float acc[4][4];
    #pragma unroll
    for (int i = 0; i < 4; i++)
        #pragma unroll
        for (int j = 0; j < 4; j++) acc[i][j] = 0.f;

    for (int k0 = 0; k0 < D; k0 += 16) {
        float4 av  = *(const float4*)(A  + (size_t)lr * D + k0 + lk);
        float4 wv  = *(const float4*)(w3 + k0 + lk);
        As[lk + 0][lr] = av.x * wv.x;
        As[lk + 1][lr] = av.y * wv.y;
        As[lk + 2][lr] = av.z * wv.z;
        As[lk + 3][lr] = av.w * wv.w;
        float4 bv = *(const float4*)(Bq + (size_t)lr * D + k0 + lk);
        Bs[lk + 0][lr] = bv.x;
        Bs[lk + 1][lr] = bv.y;
        Bs[lk + 2][lr] = bv.z;
        Bs[lk + 3][lr] = bv.w;
        __syncthreads();
        #pragma unroll
        for (int kk = 0; kk < 16; kk++) {
            float4 a4 = *(const float4*)&As[kk][tm];
            float4 b4 = *(const float4*)&Bs[kk][tn];
            acc[0][0] += a4.x * b4.x; acc[0][1] += a4.x * b4.y;
            acc[0][2] += a4.x * b4.z; acc[0][3] += a4.x * b4.w;
            acc[1][0] += a4.y * b4.x; acc[1][1] += a4.y * b4.y;
            acc[1][2] += a4.y * b4.z; acc[1][3] += a4.y * b4.w;
            acc[2][0] += a4.z * b4.x; acc[2][1] += a4.z * b4.y;
            acc[2][2] += a4.z * b4.z; acc[2][3] += a4.z * b4.w;
            acc[3][0] += a4.w * b4.x; acc[3][1] += a4.w * b4.y;
            acc[3][2] += a4.w * b4.z; acc[3][3] += a4.w * b4.w;
        }
        __syncthreads();
    }
    float ar[4], bc[4];
    #pragma unroll
    for (int i = 0; i < 4; i++) ar[i] = g_a[b * C + c0 + tm + i];
    #pragma unroll
    for (int j = 0; j < 4; j++) bc[j] = g_bq[b * Q + q0 + tn + j];
    #pragma unroll
    for (int i = 0; i < 4; i++) {
        float4 v;
        v.x = acc[i][0] + ar[i] + bc[0];
        v.y = acc[i][1] + ar[i] + bc[1];
        v.z = acc[i][2] + ar[i] + bc[2];
        v.w = acc[i][3] + ar[i] + bc[3];
        *(float4*)(g_sim + ((size_t)b * C + c0 + tm + i) * Q + q0 + tn) = v;
    }
}

// ---------------- K3: S_max[b,c] = max over q of raw sim ----------------
__global__ void k_rowmax() {
    int r = blockIdx.x * blockDim.x + threadIdx.x;
    if (r >= B * C) return;
    const float4* p = (const float4*)(g_sim + (size_t)r * Q);
    float m = -3.4e38f;
    #pragma unroll 8
    for (int i = 0; i < Q / 4; i++) {
        float4 v = p[i];
        m = fmaxf(m, fmaxf(fmaxf(v.x, v.y), fmaxf(v.z, v.w)));
    }
    g_smax[r] = m;
}

// ---------------- K4: column max & sum over c (masked) ----------------
__global__ void k_colstats(const int* __restrict__ qmask) {
    const int b  = blockIdx.y;
    const int tx = threadIdx.x;       // q within chunk of 32
    const int ty = threadIdx.y;       // c stride 8
    const int q  = blockIdx.x * 32 + tx;
    const int qm = qmask[b * Q + q];
    __shared__ float red[8][32];
    float m = -3.4e38f;
    for (int c = ty; c < C; c += 8) {
        float v = g_sim[((size_t)b * C + c) * Q + q];
        float ms = qm ? v : NEGBIG;
        m = fmaxf(m, ms);
    }
    red[ty][tx] = m;
    __syncthreads();
    if (ty == 0) {
        #pragma unroll
        for (int k = 1; k < 8; k++) m = fmaxf(m, red[k][tx]);
        red[0][tx] = m;
    }
    __syncthreads();
    m = red[0][tx];
    __syncthreads();
    float s = 0.f;
    for (int c = ty; c < C; c += 8) {
        float v = g_sim[((size_t)b * C + c) * Q + q];
        float ms = qm ? v : NEGBIG;
        s += expf(ms - m);
    }
    red[ty][tx] = s;
    __syncthreads();
    if (ty == 0) {
        #pragma unroll
        for (int k = 1; k < 8; k++) s += red[k][tx];
        g_colmax[b * Q + q] = m;
        g_colsum[b * Q + q] = s;
    }
}

// ---------------- K5: convert sim -> dist in place ----------------
__global__ void k_dist(const int* __restrict__ qmask) {
    int idx = blockIdx.x * blockDim.x + threadIdx.x;
    if (idx >= B * C * Q) return;
    int q  = idx & (Q - 1);
    int b  = idx / (C * Q);
    float v  = g_sim[idx];
    int   qm = qmask[b * Q + q];
    float ms = qm ? v : NEGBIG;
    g_sim[idx] = expf(ms - g_colmax[b * Q + q]) / g_colsum[b * Q + q];
}

// ---------------- K6: c_dash softmax weights over c ----------------
__global__ __launch_bounds__(512) void k_cweights(const int* __restrict__ cmask) {
    const int b = blockIdx.x;
    const int t = threadIdx.x;  // 512 = C
    __shared__ float red[512];
    float v  = g_smax[b * C + t];
    int   cm = cmask[b * C + t];
    float ms = cm ? v : NEGBIG;
    red[t] = ms;
    __syncthreads();
    for (int o = 256; o; o >>= 1) {
        if (t < o) red[t] = fmaxf(red[t], red[t + o]);
        __syncthreads();
    }
    float M = red[0];
    __syncthreads();
    float e = expf(ms - M);
    red[t] = e;
    __syncthreads();
    for (int o = 256; o; o >>= 1) {
        if (t < o) red[t] += red[t + o];
        __syncthreads();
    }
    float S = red[0];
    g_cdw[b * C + t] = e / S;
}

// ---------------- K7: c_dash[b,d] = sum_c w[c] * cont[b,c,d] ----------------
__global__ __launch_bounds__(256) void k_cdash(const float* __restrict__ cont) {
    const int b = blockIdx.y;
    const int d = blockIdx.x * 256 + threadIdx.x;   // 3 blocks cover 768
    __shared__ float w[C];
    for (int c = threadIdx.x; c < C; c += 256) w[c] = g_cdw[b * C + c];
    __syncthreads();
    float acc = 0.f;
    const float* base = cont + (size_t)b * C * D + d;
    for (int c = 0; c < C; c++) acc += w[c] * base[(size_t)c * D];
    g_cdash[b * D + d] = acc;
}

// ---------------- K8: c2q GEMM + full epilogue ----------------
// c2q[b,c,d] = sum_q dist[b,c,q] * ques[b,q,d]; M=C=512, N=D=768, K=Q=128
__global__ __launch_bounds__(256) void k_c2q(const float* __restrict__ cont,
                                             const float* __restrict__ ques,
                                             float* __restrict__ out) {
    __shared__ float As[16][64];  // [k][c]  (dist)
    __shared__ float Bs[16][64];  // [k][d]  (ques)
    const int b  = blockIdx.z;
    const int c0 = blockIdx.x * 64;
    const int d0 = blockIdx.y * 64;
    const float* A  = g_sim + ((size_t)b * C + c0) * Q;
    const int t = threadIdx.x;
    const int ar = t >> 2;          // 0..63 (c)
    const int ak = (t & 3) * 4;
    const int kr = t >> 4;          // 0..15 (q row for B load)
    const int kc = (t & 15) * 4;    // 0..60 (d col)
    const int tm = (t >> 4) * 4;
    const int tn = (t & 15) * 4;

    float acc[4][4];
    #pragma unroll
    for (int i = 0; i < 4; i++)
        #pragma unroll
        for (int j = 0; j < 4; j++) acc[i][j] = 0.f;

    for (int k0 = 0; k0 < Q; k0 += 16) {
        float4 av = *(const float4*)(A + (size_t)ar * Q + k0 + ak);
        As[ak + 0][ar] = av.x;
        As[ak + 1][ar] = av.y;
        As[ak + 2][ar] = av.z;
        As[ak + 3][ar] = av.w;
        float4 bv = *(const float4*)(ques + ((size_t)b * Q + k0 + kr) * D + d0 + kc);
        *(float4*)&Bs[kr][kc] = bv;
        __syncthreads();
        #pragma unroll
        for (int kk = 0; kk < 16; kk++) {
            float4 a4 = *(const float4*)&As[kk][tm];
            float4 b4 = *(const float4*)&Bs[kk][tn];
            acc[0][0] += a4.x * b4.x; acc[0][1] += a4.x * b4.y;
            acc[0][2] += a4.x * b4.z; acc[0][3] += a4.x * b4.w;
            acc[1][0] += a4.y * b4.x; acc[1][1] += a4.y * b4.y;
            acc[1][2] += a4.y * b4.z; acc[1][3] += a4.y * b4.w;
            acc[2][0] += a4.z * b4.x; acc[2][1] += a4.z * b4.y;
            acc[2][2] += a4.z * b4.z; acc[2][3] += a4.z * b4.w;
            acc[3][0] += a4.w * b4.x; acc[3][1] += a4.w * b4.y;
            acc[3][2] += a4.w * b4.z; acc[3][3] += a4.w * b4.w;
        }
        __syncthreads();
    }

    // epilogue: out = concat[cont, c2q, cont*c2q, cont*c_dash]
    float4 cd4 = *(const float4*)(g_cdash + b * D + d0 + tn);
    #pragma unroll
    for (int i = 0; i < 4; i++) {
        const int c = c0 + tm + i;
        float4 ct = *(const float4*)(cont + ((size_t)b * C + c) * D + d0 + tn);
        float4 c2q4;
        c2q4.x = acc[i][0]; c2q4.y = acc[i][1]; c2q4.z = acc[i][2]; c2q4.w = acc[i][3];
        float4 m1;  // cont * c2q
        m1.x = ct.x * c2q4.x; m1.y = ct.y * c2q4.y; m1.z = ct.z * c2q4.z; m1.w = ct.w * c2q4.w;
        float4 m2;  // cont * c_dash
        m2.x = ct.x * cd4.x; m2.y = ct.y * cd4.y; m2.z = ct.z * cd4.z; m2.w = ct.w * cd4.w;
        float* ob = out + ((size_t)b * C + c) * OD + d0 + tn;
        *(float4*)(ob)            = ct;
        *(float4*)(ob + D)        = c2q4;
        *(float4*)(ob + 2 * D)    = m1;
        *(float4*)(ob + 3 * D)    = m2;
    }
}

// ---------------- launch ----------------
extern "C" void kernel_launch(void* const* d_in, const int* in_sizes, int n_in,
                              void* d_out, int out_size) {
    const float* cont  = (const float*)d_in[0];
    const int*   cmask = (const int*)d_in[1];
    const float* ques  = (const float*)d_in[2];
    const int*   qmask = (const int*)d_in[3];
    const float* SW    = (const float*)d_in[4];
    float* out = (float*)d_out;

    (void)in_sizes; (void)n_in; (void)out_size;

    {   // K1: row dots
        int warps = B * C + B * Q;          // 20480
        int threads = warps * 32;
        k_rowdots<<<(threads + 255) / 256, 256>>>(cont, ques, SW);
    }
    {   // K2: sim GEMM
        dim3 g(C / 64, Q / 64, B);
        k_sim<<<g, 256>>>(cont, ques, SW);
    }
    {   // K3: row max
        k_rowmax<<<(B * C + 255) / 256, 256>>>();
    }
    {   // K4: col stats
        dim3 g(Q / 32, B);
        dim3 t(32, 8);
        k_colstats<<<g, t>>>(qmask);
    }
    {   // K5: dist in place
        k_dist<<<(B * C * Q + 255) / 256, 256>>>(qmask);
    }
    {   // K6: c_dash weights
        k_cweights<<<B, 512>>>(cmask);
    }
    {   // K7: c_dash
        dim3 g(D / 256, B);
        k_cdash<<<g, 256>>>(cont);
    }
    {   // K8: c2q + epilogue
        dim3 g(C / 64, D / 64, B);
        k_c2q<<<g, 256>>>(cont, ques, out);
    }
}

// round 2
// speedup vs baseline: 1.1672x; 1.1672x over previous
#include <cuda_runtime.h>
#include <math.h>
#include <stdint.h>

#define B 32
#define C 512
#define Q 128
#define D 768
#define OD (4*D)   // 3072
#define NEGBIG (-1e30f)

// ---------------- scratch ----------------
__device__ float g_sim[(size_t)B*C*Q];     // sim, later overwritten with e=exp(sim-M)
__device__ float g_a[B*C];                 // c . w1
__device__ float g_bq[B*Q];                // q . w2
__device__ float g_smaxp[2*B*C];           // partial row max per (b, q-tile, c)
__device__ float g_rS[B*Q];                // 1 / colsum
__device__ float g_cdw[B*C];               // c_dash softmax weights
__device__ float g_cdash[B*D];             // c_dash per batch

// ---------------- packed f32x2 helpers ----------------
#define PACK2(u, x) do { unsigned _xi = __float_as_uint(x); \
    asm("mov.b64 %0, {%1, %2};" : "=l"(u) : "r"(_xi), "r"(_xi)); } while(0)
#define FMA2(d, a, bb) \
    asm("fma.rn.f32x2 %0, %1, %2, %3;" : "=l"(d) : "l"(a), "l"(bb), "l"(d))
#define UNPACK2(lo, hi, u) do { unsigned _l, _h; \
    asm("mov.b64 {%0, %1}, %2;" : "=r"(_l), "=r"(_h) : "l"(u)); \
    lo = __uint_as_float(_l); hi = __uint_as_float(_h); } while(0)

// ---------------- K1: row dots (c.w1, q.w2) ----------------
__global__ void k_rowdots(const float* __restrict__ cont,
                          const float* __restrict__ ques,
                          const float* __restrict__ SW) {
    int warp = (blockIdx.x * blockDim.x + threadIdx.x) >> 5;
    int lane = threadIdx.x & 31;
    const int NC = B * C;
    float acc = 0.f;
    if (warp < NC) {
        const float* row = cont + (size_t)warp * D;
        #pragma unroll 4
        for (int d = lane; d < D; d += 32) acc += row[d] * SW[d];
        #pragma unroll
        for (int o = 16; o; o >>= 1) acc += __shfl_xor_sync(0xffffffffu, acc, o);
        if (!lane) g_a[warp] = acc;
    } else if (warp < NC + B * Q) {
        int r = warp - NC;
        const float* row = ques + (size_t)r * D;
        const float* w = SW + D;
        #pragma unroll 4
        for (int d = lane; d < D; d += 32) acc += row[d] * w[d];
        #pragma unroll
        for (int o = 16; o; o >>= 1) acc += __shfl_xor_sync(0xffffffffu, acc, o);
        if (!lane) g_bq[r] = acc;
    }
}

// ---------------- K2: sim GEMM (128x64 tile, f32x2, fused row-max) ----------------
// sim[b,c,q] = a[c] + bq[q] + sum_d (cont[c,d]*w3[d]) * ques[q,d]
__global__ __launch_bounds__(256) void k_sim(const float* __restrict__ cont,
                                             const float* __restrict__ ques,
                                             const float* __restrict__ SW) {
    __shared__ __align__(16) float As[16][128];  // [k][c]
    __shared__ __align__(16) float Bs[16][64];   // [k][q]
    const int b  = blockIdx.z;
    const int c0 = blockIdx.x * 128;
    const int q0 = blockIdx.y * 64;
    const int qt = blockIdx.y;
    const int t  = threadIdx.x;
    const int tx = t & 15, ty = t >> 4;
    const int tm = ty * 8, tn = tx * 4;
    const int lrA = t >> 1, lkA = (t & 1) * 8;
    const int lrB = t >> 2, lkB = (t & 3) * 4;

    const float* Ag = cont + ((size_t)b * C + c0 + lrA) * D;
    const float* Bg = ques + ((size_t)b * Q + q0 + lrB) * D;
    const float* w3 = SW + 2 * D;

    uint64_t acc[4][4];
    #pragma unroll
    for (int i = 0; i < 4; i++)
        #pragma unroll
        for (int j = 0; j < 4; j++) acc[i][j] = 0ull;

    for (int k0 = 0; k0 < D; k0 += 16) {
        float4 a0 = *(const float4*)(Ag + k0 + lkA);
        float4 a1 = *(const float4*)(Ag + k0 + lkA + 4);
        float4 w0 = *(const float4*)(w3 + k0 + lkA);
        float4 w1 = *(const float4*)(w3 + k0 + lkA + 4);
        As[lkA + 0][lrA] = a0.x * w0.x;
        As[lkA + 1][lrA] = a0.y * w0.y;
        As[lkA + 2][lrA] = a0.z * w0.z;
        As[lkA + 3][lrA] = a0.w * w0.w;
        As[lkA + 4][lrA] = a1.x * w1.x;
        As[lkA + 5][lrA] = a1.y * w1.y;
        As[lkA + 6][lrA] = a1.z * w1.z;
        As[lkA + 7][lrA] = a1.w * w1.w;
        float4 bv = *(const float4*)(Bg + k0 + lkB);
        Bs[lkB + 0][lrB] = bv.x;
        Bs[lkB + 1][lrB] = bv.y;
        Bs[lkB + 2][lrB] = bv.z;
        Bs[lkB + 3][lrB] = bv.w;
        __syncthreads();
        #pragma unroll
        for (int kk = 0; kk < 16; kk++) {
            ulonglong2 aA = *(const ulonglong2*)&As[kk][tm];
            ulonglong2 aB = *(const ulonglong2*)&As[kk][tm + 4];
            float4 b4 = *(const float4*)&Bs[kk][tn];
            uint64_t bb0, bb1, bb2, bb3;
            PACK2(bb0, b4.x); PACK2(bb1, b4.y); PACK2(bb2, b4.z); PACK2(bb3, b4.w);
            FMA2(acc[0][0], aA.x, bb0); FMA2(acc[0][1], aA.x, bb1);
            FMA2(acc[0][2], aA.x, bb2); FMA2(acc[0][3], aA.x, bb3);
            FMA2(acc[1][0], aA.y, bb0); FMA2(acc[1][1], aA.y, bb1);
            FMA2(acc[1][2], aA.y, bb2); FMA2(acc[1][3], aA.y, bb3);
            FMA2(acc[2][0], aB.x, bb0); FMA2(acc[2][1], aB.x, bb1);
            FMA2(acc[2][2], aB.x, bb2); FMA2(acc[2][3], aB.x, bb3);
            FMA2(acc[3][0], aB.y, bb0); FMA2(acc[3][1], aB.y, bb1);
            FMA2(acc[3][2], aB.y, bb2); FMA2(acc[3][3], aB.y, bb3);
        }
        __syncthreads();
    }

    // epilogue: add biases, write sim, fused partial row-max
    float bc[4];
    #pragma unroll
    for (int j = 0; j < 4; j++) bc[j] = g_bq[b * Q + q0 + tn + j];
    float (*red)[16] = (float (*)[16])&As[0][0];   // reuse As: [128][16]

    #pragma unroll
    for (int p = 0; p < 4; p++) {
        float lo[4], hi[4];
        #pragma unroll
        for (int n = 0; n < 4; n++) UNPACK2(lo[n], hi[n], acc[p][n]);
        int r0 = tm + 2 * p;
        float ar0 = g_a[b * C + c0 + r0];
        float ar1 = g_a[b * C + c0 + r0 + 1];
        float4 v0, v1;
        v0.x = lo[0] + ar0 + bc[0]; v0.y = lo[1] + ar0 + bc[1];
        v0.z = lo[2] + ar0 + bc[2]; v0.w = lo[3] + ar0 + bc[3];
        v1.x = hi[0] + ar1 + bc[0]; v1.y = hi[1] + ar1 + bc[1];
        v1.z = hi[2] + ar1 + bc[2]; v1.w = hi[3] + ar1 + bc[3];
        *(float4*)(g_sim + ((size_t)b * C + c0 + r0) * Q + q0 + tn) = v0;
        *(float4*)(g_sim + ((size_t)b * C + c0 + r0 + 1) * Q + q0 + tn) = v1;
        red[r0][tx]     = fmaxf(fmaxf(v0.x, v0.y), fmaxf(v0.z, v0.w));
        red[r0 + 1][tx] = fmaxf(fmaxf(v1.x, v1.y), fmaxf(v1.z, v1.w));
    }
    __syncthreads();
    if (t < 128) {
        float m = red[t][0];
        #pragma unroll
        for (int k = 1; k < 16; k++) m = fmaxf(m, red[t][k]);
        g_smaxp[((size_t)b * 2 + qt) * C + c0 + t] = m;
    }
}

// ---------------- K3: column softmax stats + write e in place ----------------
__global__ void k_colstats(const int* __restrict__ qmask) {
    const int b  = blockIdx.y;
    const int tx = threadIdx.x, ty = threadIdx.y;
    const int q  = blockIdx.x * 32 + tx;
    const int qm = qmask[b * Q + q];
    __shared__ float red[8][32];
    float m = -3.4e38f;
    for (int c = ty; c < C; c += 8) {
        float v = g_sim[((size_t)b * C + c) * Q + q];
        m = fmaxf(m, qm ? v : NEGBIG);
    }
    red[ty][tx] = m;
    __syncthreads();
    if (ty == 0) {
        #pragma unroll
        for (int k = 1; k < 8; k++) m = fmaxf(m, red[k][tx]);
        red[0][tx] = m;
    }
    __syncthreads();
    m = red[0][tx];
    __syncthreads();
    float s = 0.f;
    for (int c = ty; c < C; c += 8) {
        size_t idx = ((size_t)b * C + c) * Q + q;
        float v = g_sim[idx];
        float e = expf((qm ? v : NEGBIG) - m);
        g_sim[idx] = e;
        s += e;
    }
    red[ty][tx] = s;
    __syncthreads();
    if (ty == 0) {
        #pragma unroll
        for (int k = 1; k < 8; k++) s += red[k][tx];
        g_rS[b * Q + q] = 1.f / s;
    }
}

// ---------------- K4: c_dash softmax weights over c ----------------
__global__ __launch_bounds__(512) void k_cweights(const int* __restrict__ cmask) {
    const int b = blockIdx.x;
    const int t = threadIdx.x;   // 512 = C
    __shared__ float red[512];
    float v = fmaxf(g_smaxp[((size_t)b * 2) * C + t],
                    g_smaxp[((size_t)b * 2 + 1) * C + t]);
    float ms = cmask[b * C + t] ? v : NEGBIG;
    red[t] = ms;
    __syncthreads();
    for (int o = 256; o; o >>= 1) {
        if (t < o) red[t] = fmaxf(red[t], red[t + o]);
        __syncthreads();
    }
    float M = red[0];
    __syncthreads();
    float e = expf(ms - M);
    red[t] = e;
    __syncthreads();
    for (int o = 256; o; o >>= 1) {
        if (t < o) red[t] += red[t + o];
        __syncthreads();
    }
    g_cdw[b * C + t] = e / red[0];
}

// ---------------- K5: c_dash[b,d] = sum_c w[c] * cont[b,c,d] ----------------
__global__ __launch_bounds__(256) void k_cdash(const float* __restrict__ cont) {
    const int b = blockIdx.y;
    const int d = blockIdx.x * 256 + threadIdx.x;
    __shared__ float w[C];
    for (int c = threadIdx.x; c < C; c += 256) w[c] = g_cdw[b * C + c];
    __syncthreads();
    float acc = 0.f;
    const float* base = cont + (size_t)b * C * D + d;
    for (int c = 0; c < C; c++) acc += w[c] * base[(size_t)c * D];
    g_cdash[b * D + d] = acc;
}

// ---------------- K6: c2q GEMM (128x64, f32x2, rS folded into B) + epilogue ----------------
__global__ __launch_bounds__(256) void k_c2q(const float* __restrict__ cont,
                                             const float* __restrict__ ques,
                                             float* __restrict__ out) {
    __shared__ __align__(16) float As[16][128];  // [k(q)][c] : e values
    __shared__ __align__(16) float Bs[16][64];   // [k(q)][d] : ques * rS
    const int b  = blockIdx.z;
    const int c0 = blockIdx.x * 128;
    const int d0 = blockIdx.y * 64;
    const int t  = threadIdx.x;
    const int tx = t & 15, ty = t >> 4;
    const int tm = ty * 8, tn = tx * 4;
    const int lrA = t >> 1, lkA = (t & 1) * 8;
    const int kr = t >> 4, kc = (t & 15) * 4;

    const float* Ag = g_sim + ((size_t)b * C + c0 + lrA) * Q;

    uint64_t acc[4][4];
    #pragma unroll
    for (int i = 0; i < 4; i++)
        #pragma unroll
        for (int j = 0; j < 4; j++) acc[i][j] = 0ull;

    for (int k0 = 0; k0 < Q; k0 += 16) {
        float4 e0 = *(const float4*)(Ag + k0 + lkA);
        float4 e1 = *(const float4*)(Ag + k0 + lkA + 4);
        As[lkA + 0][lrA] = e0.x;
        As[lkA + 1][lrA] = e0.y;
        As[lkA + 2][lrA] = e0.z;
        As[lkA + 3][lrA] = e0.w;
        As[lkA + 4][lrA] = e1.x;
        As[lkA + 5][lrA] = e1.y;
        As[lkA + 6][lrA] = e1.z;
        As[lkA + 7][lrA] = e1.w;
        float rs = g_rS[b * Q + k0 + kr];
        float4 qv = *(const float4*)(ques + ((size_t)b * Q + k0 + kr) * D + d0 + kc);
        qv.x *= rs; qv.y *= rs; qv.z *= rs; qv.w *= rs;
        *(float4*)&Bs[kr][kc] = qv;
        __syncthreads();
        #pragma unroll
        for (int kk = 0; kk < 16; kk++) {
            ulonglong2 aA = *(const ulonglong2*)&As[kk][tm];
            ulonglong2 aB = *(const ulonglong2*)&As[kk][tm + 4];
            float4 b4 = *(const float4*)&Bs[kk][tn];
            uint64_t bb0, bb1, bb2, bb3;
            PACK2(bb0, b4.x); PACK2(bb1, b4.y); PACK2(bb2, b4.z); PACK2(bb3, b4.w);
            FMA2(acc[0][0], aA.x, bb0); FMA2(acc[0][1], aA.x, bb1);
            FMA2(acc[0][2], aA.x, bb2); FMA2(acc[0][3], aA.x, bb3);
            FMA2(acc[1][0], aA.y, bb0); FMA2(acc[1][1], aA.y, bb1);
            FMA2(acc[1][2], aA.y, bb2); FMA2(acc[1][3], aA.y, bb3);
            FMA2(acc[2][0], aB.x, bb0); FMA2(acc[2][1], aB.x, bb1);
            FMA2(acc[2][2], aB.x, bb2); FMA2(acc[2][3], aB.x, bb3);
            FMA2(acc[3][0], aB.y, bb0); FMA2(acc[3][1], aB.y, bb1);
            FMA2(acc[3][2], aB.y, bb2); FMA2(acc[3][3], aB.y, bb3);
        }
        __syncthreads();
    }

    // epilogue: out = concat[cont, c2q, cont*c2q, cont*c_dash]
    float4 cd4 = *(const float4*)(g_cdash + (size_t)b * D + d0 + tn);
    #pragma unroll
    for (int p = 0; p < 4; p++) {
        float lo[4], hi[4];
        #pragma unroll
        for (int n = 0; n < 4; n++) UNPACK2(lo[n], hi[n], acc[p][n]);
        #pragma unroll
        for (int h = 0; h < 2; h++) {
            const int c = c0 + tm + 2 * p + h;
            float4 c2q4;
            if (h == 0) { c2q4.x = lo[0]; c2q4.y = lo[1]; c2q4.z = lo[2]; c2q4.w = lo[3]; }
            else        { c2q4.x = hi[0]; c2q4.y = hi[1]; c2q4.z = hi[2]; c2q4.w = hi[3]; }
            float4 ct = *(const float4*)(cont + ((size_t)b * C + c) * D + d0 + tn);
            float4 m1, m2;
            m1.x = ct.x * c2q4.x; m1.y = ct.y * c2q4.y;
            m1.z = ct.z * c2q4.z; m1.w = ct.w * c2q4.w;
            m2.x = ct.x * cd4.x;  m2.y = ct.y * cd4.y;
            m2.z = ct.z * cd4.z;  m2.w = ct.w * cd4.w;
            float* ob = out + ((size_t)b * C + c) * OD + d0 + tn;
            *(float4*)(ob)         = ct;
            *(float4*)(ob + D)     = c2q4;
            *(float4*)(ob + 2 * D) = m1;
            *(float4*)(ob + 3 * D) = m2;
        }
    }
}

// ---------------- launch ----------------
extern "C" void kernel_launch(void* const* d_in, const int* in_sizes, int n_in,
                              void* d_out, int out_size) {
    const float* cont  = (const float*)d_in[0];
    const int*   cmask = (const int*)d_in[1];
    const float* ques  = (const float*)d_in[2];
    const int*   qmask = (const int*)d_in[3];
    const float* SW    = (const float*)d_in[4];
    float* out = (float*)d_out;
    (void)in_sizes; (void)n_in; (void)out_size;

    {   // K1
        int warps = B * C + B * Q;
        k_rowdots<<<(warps * 32 + 255) / 256, 256>>>(cont, ques, SW);
    }
    {   // K2
        dim3 g(C / 128, Q / 64, B);
        k_sim<<<g, 256>>>(cont, ques, SW);
    }
    {   // K3
        dim3 g(Q / 32, B);
        dim3 th(32, 8);
        k_colstats<<<g, th>>>(qmask);
    }
    {   // K4
        k_cweights<<<B, 512>>>(cmask);
    }
    {   // K5
        dim3 g(D / 256, B);
        k_cdash<<<g, 256>>>(cont);
    }
    {   // K6
        dim3 g(C / 128, D / 64, B);
        k_c2q<<<g, 256>>>(cont, ques, out);
    }
}

// round 4
// speedup vs baseline: 1.3270x; 1.1369x over previous
#include <cuda_runtime.h>
#include <cuda_bf16.h>
#include <math.h>
#include <stdint.h>

#define B 32
#define C 512
#define Q 128
#define D 768
#define OD (4*D)
#define NEGBIG (-1e30f)

// ---------------- scratch ----------------
__device__ float g_sim [(size_t)B*C*Q];   // sim, then e=exp(sim-M) in place
__device__ float g_rS  [B*Q];             // 1/colsum
__device__ float g_smax[B*C];
__device__ float g_cdash[B*D];

// ---------------- helpers ----------------
__device__ __forceinline__ unsigned smem_u32(const void* p) {
    unsigned a;
    asm("{ .reg .u64 tmp; cvta.to.shared.u64 tmp, %1; cvt.u32.u64 %0, tmp; }" : "=r"(a) : "l"(p));
    return a;
}
__device__ __forceinline__ void ldm_x4(unsigned* r, const void* p) {
    unsigned a = smem_u32(p);
    asm volatile("ldmatrix.sync.aligned.m8n8.x4.shared.b16 {%0,%1,%2,%3}, [%4];"
        : "=r"(r[0]), "=r"(r[1]), "=r"(r[2]), "=r"(r[3]) : "r"(a));
}
__device__ __forceinline__ void ldm_x4t(unsigned* r, const void* p) {
    unsigned a = smem_u32(p);
    asm volatile("ldmatrix.sync.aligned.m8n8.x4.trans.shared.b16 {%0,%1,%2,%3}, [%4];"
        : "=r"(r[0]), "=r"(r[1]), "=r"(r[2]), "=r"(r[3]) : "r"(a));
}
__device__ __forceinline__ void mma_bf16(float* d, const unsigned* a, unsigned b0, unsigned b1) {
    asm volatile("mma.sync.aligned.m16n8k16.row.col.f32.bf16.bf16.f32 "
        "{%0,%1,%2,%3}, {%4,%5,%6,%7}, {%8,%9}, {%0,%1,%2,%3};"
        : "+f"(d[0]), "+f"(d[1]), "+f"(d[2]), "+f"(d[3])
        : "r"(a[0]), "r"(a[1]), "r"(a[2]), "r"(a[3]), "r"(b0), "r"(b1));
}
// split two fp32 into bf16x2 hi and bf16x2 lo
__device__ __forceinline__ void split2(float x0, float x1, unsigned& h, unsigned& l) {
    __nv_bfloat16 h0 = __float2bfloat16(x0), h1 = __float2bfloat16(x1);
    float r0 = x0 - __bfloat162float(h0), r1 = x1 - __bfloat162float(h1);
    __nv_bfloat16 l0 = __float2bfloat16(r0), l1 = __float2bfloat16(r1);
    unsigned short a0 = *(unsigned short*)&h0, a1 = *(unsigned short*)&h1;
    unsigned short b0 = *(unsigned short*)&l0, b1 = *(unsigned short*)&l1;
    h = (unsigned)a0 | ((unsigned)a1 << 16);
    l = (unsigned)b0 | ((unsigned)b1 << 16);
}

// ================= K1: sim GEMM (mma.sync bf16 split) =================
// sim[b,c,q] = (c.w1)[c] + (q.w2)[q] + sum_d (cont*w3)[c,d]*ques[q,d]
// tile 128(c) x 128(q), BK=32, 8 warps (wm=wid&3 -> 32 rows, wn=wid>>2 -> 64 cols)
__global__ __launch_bounds__(256) void k_sim_mma(const float* __restrict__ cont,
                                                 const float* __restrict__ ques,
                                                 const float* __restrict__ SW) {
    __shared__ __nv_bfloat16 Ah[128][40], Al[128][40], Bh[128][40], Bl[128][40];
    __shared__ float sm_a[128], sm_bq[128], sm_rmax[2][128];
    const int cb = blockIdx.x, b = blockIdx.y;
    const int t = threadIdx.x, lane = t & 31, wid = t >> 5;
    const int wm = wid & 3, wn = wid >> 2;
    const int row = t >> 1, half = t & 1;

    const float* Ag = cont + ((size_t)(b * C + cb * 128 + row)) * D + half * 16;
    const float* Bg = ques + ((size_t)(b * Q + row)) * D + half * 16;
    const float* w1 = SW;
    const float* w2 = SW + D;
    const float* w3 = SW + 2 * D;

    float acc[2][8][4];
    #pragma unroll
    for (int i = 0; i < 2; i++)
        #pragma unroll
        for (int j = 0; j < 8; j++)
            #pragma unroll
            for (int k = 0; k < 4; k++) acc[i][j][k] = 0.f;

    float a_part = 0.f, bq_part = 0.f;
    float4 ra[4], rb[4];
    #pragma unroll
    for (int j = 0; j < 4; j++) {
        ra[j] = *(const float4*)(Ag + j * 4);
        rb[j] = *(const float4*)(Bg + j * 4);
    }

    for (int k0 = 0; k0 < D; k0 += 32) {
        if (k0) __syncthreads();
        #pragma unroll
        for (int j = 0; j < 4; j++) {
            int col = half * 16 + j * 4;
            float4 w3v = *(const float4*)(w3 + k0 + col);
            float4 w1v = *(const float4*)(w1 + k0 + col);
            float4 w2v = *(const float4*)(w2 + k0 + col);
            a_part  += ra[j].x * w1v.x + ra[j].y * w1v.y + ra[j].z * w1v.z + ra[j].w * w1v.w;
            bq_part += rb[j].x * w2v.x + rb[j].y * w2v.y + rb[j].z * w2v.z + rb[j].w * w2v.w;
            unsigned h0, l0, h1, l1;
            split2(ra[j].x * w3v.x, ra[j].y * w3v.y, h0, l0);
            split2(ra[j].z * w3v.z, ra[j].w * w3v.w, h1, l1);
            *(unsigned*)&Ah[row][col]     = h0;  *(unsigned*)&Al[row][col]     = l0;
            *(unsigned*)&Ah[row][col + 2] = h1;  *(unsigned*)&Al[row][col + 2] = l1;
            split2(rb[j].x, rb[j].y, h0, l0);
            split2(rb[j].z, rb[j].w, h1, l1);
            *(unsigned*)&Bh[row][col]     = h0;  *(unsigned*)&Bl[row][col]     = l0;
            *(unsigned*)&Bh[row][col + 2] = h1;  *(unsigned*)&Bl[row][col + 2] = l1;
        }
        __syncthreads();
        if (k0 + 32 < D) {
            #pragma unroll
            for (int j = 0; j < 4; j++) {
                ra[j] = *(const float4*)(Ag + k0 + 32 + j * 4);
                rb[j] = *(const float4*)(Bg + k0 + 32 + j * 4);
            }
        }
        #pragma unroll
        for (int kk = 0; kk < 2; kk++) {
            const int kb = kk * 16;
            unsigned afh[2][4], afl[2][4];
            #pragma unroll
            for (int mt = 0; mt < 2; mt++) {
                ldm_x4(afh[mt], &Ah[wm * 32 + mt * 16 + (lane & 15)][kb + (lane >> 4) * 8]);
                ldm_x4(afl[mt], &Al[wm * 32 + mt * 16 + (lane & 15)][kb + (lane >> 4) * 8]);
            }
            #pragma unroll
            for (int ng = 0; ng < 4; ng++) {
                unsigned bfh[4], bfl[4];
                ldm_x4(bfh, &Bh[wn * 64 + ng * 16 + (lane & 15)][kb + (lane >> 4) * 8]);
                ldm_x4(bfl, &Bl[wn * 64 + ng * 16 + (lane & 15)][kb + (lane >> 4) * 8]);
                #pragma unroll
                for (int h = 0; h < 2; h++) {
                    const int nt = ng * 2 + h;
                    #pragma unroll
                    for (int mt = 0; mt < 2; mt++) {
                        mma_bf16(acc[mt][nt], afh[mt], bfh[h], bfh[2 + h]);
                        mma_bf16(acc[mt][nt], afh[mt], bfl[h], bfl[2 + h]);
                        mma_bf16(acc[mt][nt], afl[mt], bfh[h], bfh[2 + h]);
                    }
                }
            }
        }
    }

    // reduce bias dots (pairs t, t^1 share a row)
    a_part  += __shfl_xor_sync(0xffffffffu, a_part, 1);
    bq_part += __shfl_xor_sync(0xffffffffu, bq_part, 1);
    if (half == 0) { sm_a[row] = a_part; sm_bq[row] = bq_part; }
    __syncthreads();

    // epilogue: bias add, store sim, row max
    #pragma unroll
    for (int mt = 0; mt < 2; mt++) {
        const int r0 = wm * 32 + mt * 16 + (lane >> 2);
        const float a0 = sm_a[r0], a1 = sm_a[r0 + 8];
        float m0 = -3.4e38f, m1 = -3.4e38f;
        #pragma unroll
        for (int nt = 0; nt < 8; nt++) {
            const int q0 = wn * 64 + nt * 8 + (lane & 3) * 2;
            const float bq0 = sm_bq[q0], bq1 = sm_bq[q0 + 1];
            float v00 = acc[mt][nt][0] + a0 + bq0;
            float v01 = acc[mt][nt][1] + a0 + bq1;
            float v10 = acc[mt][nt][2] + a1 + bq0;
            float v11 = acc[mt][nt][3] + a1 + bq1;
            float2* p0 = (float2*)(g_sim + ((size_t)(b * C + cb * 128 + r0)) * Q + q0);
            float2* p1 = (float2*)(g_sim + ((size_t)(b * C + cb * 128 + r0 + 8)) * Q + q0);
            *p0 = make_float2(v00, v01);
            *p1 = make_float2(v10, v11);
            m0 = fmaxf(m0, fmaxf(v00, v01));
            m1 = fmaxf(m1, fmaxf(v10, v11));
        }
        m0 = fmaxf(m0, __shfl_xor_sync(0xffffffffu, m0, 1));
        m0 = fmaxf(m0, __shfl_xor_sync(0xffffffffu, m0, 2));
        m1 = fmaxf(m1, __shfl_xor_sync(0xffffffffu, m1, 1));
        m1 = fmaxf(m1, __shfl_xor_sync(0xffffffffu, m1, 2));
        if ((lane & 3) == 0) {
            sm_rmax[wn][r0]     = m0;
            sm_rmax[wn][r0 + 8] = m1;
        }
    }
    __syncthreads();
    if (t < 128)
        g_smax[b * C + cb * 128 + t] = fmaxf(sm_rmax[0][t], sm_rmax[1][t]);
}

// ================= K2: column softmax stats, e in place =================
__global__ void k_colstats(const int* __restrict__ qmask) {
    const int b  = blockIdx.y;
    const int tx = threadIdx.x, ty = threadIdx.y;
    const int q  = blockIdx.x * 32 + tx;
    const int qm = qmask[b * Q + q];
    __shared__ float red[8][32];
    float m = -3.4e38f;
    for (int c = ty; c < C; c += 8) {
        float v = g_sim[((size_t)(b * C + c)) * Q + q];
        m = fmaxf(m, qm ? v : NEGBIG);
    }
    red[ty][tx] = m;
    __syncthreads();
    if (ty == 0) {
        #pragma unroll
        for (int k = 1; k < 8; k++) m = fmaxf(m, red[k][tx]);
        red[0][tx] = m;
    }
    __syncthreads();
    m = red[0][tx];
    __syncthreads();
    float s = 0.f;
    for (int c = ty; c < C; c += 8) {
        size_t idx = ((size_t)(b * C + c)) * Q + q;
        float v = g_sim[idx];
        float e = expf((qm ? v : NEGBIG) - m);
        g_sim[idx] = e;
        s += e;
    }
    red[ty][tx] = s;
    __syncthreads();
    if (ty == 0) {
        #pragma unroll
        for (int k = 1; k < 8; k++) s += red[k][tx];
        g_rS[b * Q + q] = 1.f / s;
    }
}

// ================= K3: c_dash (weights inline) =================
__global__ __launch_bounds__(256) void k_cdashW(const float* __restrict__ cont,
                                                const int* __restrict__ cmask) {
    __shared__ float red[256];
    __shared__ float w[512];
    const int b = blockIdx.y;
    const int t = threadIdx.x;
    float s0 = g_smax[b * C + t], s1 = g_smax[b * C + 256 + t];
    float ms0 = cmask[b * C + t] ? s0 : NEGBIG;
    float ms1 = cmask[b * C + 256 + t] ? s1 : NEGBIG;
    red[t] = fmaxf(ms0, ms1);
    __syncthreads();
    for (int o = 128; o; o >>= 1) {
        if (t < o) red[t] = fmaxf(red[t], red[t + o]);
        __syncthreads();
    }
    float M = red[0];
    __syncthreads();
    float e0 = expf(ms0 - M), e1 = expf(ms1 - M);
    red[t] = e0 + e1;
    __syncthreads();
    for (int o = 128; o; o >>= 1) {
        if (t < o) red[t] += red[t + o];
        __syncthreads();
    }
    float rS = 1.f / red[0];
    w[t] = e0 * rS;
    w[256 + t] = e1 * rS;
    __syncthreads();
    const int d = blockIdx.x * 256 + t;
    float acc = 0.f;
    const float* base = cont + (size_t)b * C * D + d;
    #pragma unroll 8
    for (int c = 0; c < C; c++) acc += w[c] * base[(size_t)c * D];
    g_cdash[b * D + d] = acc;
}

// ================= K4: c2q GEMM (mma.sync) + full epilogue =================
// c2q[b,c,d] = sum_q (e[c,q]*rS[q]) * ques[q,d];  tile 128(c) x 128(d), BK=32 over Q
__global__ __launch_bounds__(256) void k_c2q_mma(const float* __restrict__ cont,
                                                 const float* __restrict__ ques,
                                                 float* __restrict__ out) {
    __shared__ __nv_bfloat16 Ah[128][40], Al[128][40];
    __shared__ __nv_bfloat16 Bh[32][136], Bl[32][136];
    __shared__ float sm_rs[128], sm_cd[128];
    const int cb = blockIdx.x, dt = blockIdx.y, b = blockIdx.z;
    const int t = threadIdx.x, lane = t & 31, wid = t >> 5;
    const int wm = wid & 3, wn = wid >> 2;
    const int row = t >> 1, half = t & 1;       // A load mapping
    const int brow = t >> 3, bc0 = (t & 7) * 16; // B load mapping

    if (t < 128) {
        sm_rs[t] = g_rS[b * Q + t];
        sm_cd[t] = g_cdash[b * D + dt * 128 + t];
    }
    __syncthreads();

    const float* Ag = g_sim + ((size_t)(b * C + cb * 128 + row)) * Q + half * 16;
    const float* Bg = ques + ((size_t)b * Q) * D + dt * 128;

    float acc[2][8][4];
    #pragma unroll
    for (int i = 0; i < 2; i++)
        #pragma unroll
        for (int j = 0; j < 8; j++)
            #pragma unroll
            for (int k = 0; k < 4; k++) acc[i][j][k] = 0.f;

    float4 ra[4], rb[4];
    #pragma unroll
    for (int j = 0; j < 4; j++) {
        ra[j] = *(const float4*)(Ag + j * 4);
        rb[j] = *(const float4*)(Bg + (size_t)brow * D + bc0 + j * 4);
    }

    for (int k0 = 0; k0 < Q; k0 += 32) {
        if (k0) __syncthreads();
        #pragma unroll
        for (int j = 0; j < 4; j++) {
            int col = half * 16 + j * 4;
            float r0 = sm_rs[k0 + col], r1 = sm_rs[k0 + col + 1];
            float r2 = sm_rs[k0 + col + 2], r3 = sm_rs[k0 + col + 3];
            unsigned h0, l0, h1, l1;
            split2(ra[j].x * r0, ra[j].y * r1, h0, l0);
            split2(ra[j].z * r2, ra[j].w * r3, h1, l1);
            *(unsigned*)&Ah[row][col]     = h0;  *(unsigned*)&Al[row][col]     = l0;
            *(unsigned*)&Ah[row][col + 2] = h1;  *(unsigned*)&Al[row][col + 2] = l1;
            int bcol = bc0 + j * 4;
            split2(rb[j].x, rb[j].y, h0, l0);
            split2(rb[j].z, rb[j].w, h1, l1);
            *(unsigned*)&Bh[brow][bcol]     = h0;  *(unsigned*)&Bl[brow][bcol]     = l0;
            *(unsigned*)&Bh[brow][bcol + 2] = h1;  *(unsigned*)&Bl[brow][bcol + 2] = l1;
        }
        __syncthreads();
        if (k0 + 32 < Q) {
            #pragma unroll
            for (int j = 0; j < 4; j++) {
                ra[j] = *(const float4*)(Ag + k0 + 32 + j * 4);
                rb[j] = *(const float4*)(Bg + (size_t)(k0 + 32 + brow) * D + bc0 + j * 4);
            }
        }
        #pragma unroll
        for (int kk = 0; kk < 2; kk++) {
            const int kb = kk * 16;
            unsigned afh[2][4], afl[2][4];
            #pragma unroll
            for (int mt = 0; mt < 2; mt++) {
                ldm_x4(afh[mt], &Ah[wm * 32 + mt * 16 + (lane & 15)][kb + (lane >> 4) * 8]);
                ldm_x4(afl[mt], &Al[wm * 32 + mt * 16 + (lane & 15)][kb + (lane >> 4) * 8]);
            }
            #pragma unroll
            for (int ng = 0; ng < 4; ng++) {
                unsigned bfh[4], bfl[4];
                ldm_x4t(bfh, &Bh[kb + (lane & 15)][wn * 64 + ng * 16 + (lane >> 4) * 8]);
                ldm_x4t(bfl, &Bl[kb + (lane & 15)][wn * 64 + ng * 16 + (lane >> 4) * 8]);
                #pragma unroll
                for (int h = 0; h < 2; h++) {
                    const int nt = ng * 2 + h;
                    #pragma unroll
                    for (int mt = 0; mt < 2; mt++) {
                        mma_bf16(acc[mt][nt], afh[mt], bfh[2 * h], bfh[2 * h + 1]);
                        mma_bf16(acc[mt][nt], afh[mt], bfl[2 * h], bfl[2 * h + 1]);
                        mma_bf16(acc[mt][nt], afl[mt], bfh[2 * h], bfh[2 * h + 1]);
                    }
                }
            }
        }
    }

    // epilogue: out = concat[cont, c2q, cont*c2q, cont*c_dash]
    #pragma unroll
    for (int mt = 0; mt < 2; mt++) {
        const int rbase = cb * 128 + wm * 32 + mt * 16 + (lane >> 2);
        #pragma unroll
        for (int rr = 0; rr < 2; rr++) {
            const int c = rbase + rr * 8;
            const float* cr = cont + ((size_t)(b * C + c)) * D;
            float* ob = out + ((size_t)(b * C + c)) * OD;
            #pragma unroll
            for (int nt = 0; nt < 8; nt++) {
                const int dloc = wn * 64 + nt * 8 + (lane & 3) * 2;
                const int dd = dt * 128 + dloc;
                float2 ct = *(const float2*)(cr + dd);
                float2 cq = make_float2(acc[mt][nt][2 * rr], acc[mt][nt][2 * rr + 1]);
                float2 cd = *(const float2*)(sm_cd + dloc);
                float2 m1 = make_float2(ct.x * cq.x, ct.y * cq.y);
                float2 m2 = make_float2(ct.x * cd.x, ct.y * cd.y);
                *(float2*)(ob + dd)         = ct;
                *(float2*)(ob + D + dd)     = cq;
                *(float2*)(ob + 2 * D + dd) = m1;
                *(float2*)(ob + 3 * D + dd) = m2;
            }
        }
    }
}

// ---------------- launch ----------------
extern "C" void kernel_launch(void* const* d_in, const int* in_sizes, int n_in,
                              void* d_out, int out_size) {
    const float* cont  = (const float*)d_in[0];
    const int*   cmask = (const int*)d_in[1];
    const float* ques  = (const float*)d_in[2];
    const int*   qmask = (const int*)d_in[3];
    const float* SW    = (const float*)d_in[4];
    float* out = (float*)d_out;
    (void)in_sizes; (void)n_in; (void)out_size;

    {   dim3 g(C / 128, B);      k_sim_mma<<<g, 256>>>(cont, ques, SW); }
    {   dim3 g(Q / 32, B);       dim3 th(32, 8); k_colstats<<<g, th>>>(qmask); }
    {   dim3 g(D / 256, B);      k_cdashW<<<g, 256>>>(cont, cmask); }
    {   dim3 g(C / 128, D / 128, B); k_c2q_mma<<<g, 256>>>(cont, ques, out); }
}

// round 5
// speedup vs baseline: 1.3650x; 1.0286x over previous
#include <cuda_runtime.h>
#include <cuda_bf16.h>
#include <math.h>
#include <stdint.h>

#define B 32
#define C 512
#define Q 128
#define D 768
#define OD (4*D)
#define NEGBIG (-1e30f)

// ---------------- scratch ----------------
__device__ float g_sim [(size_t)B*C*Q];   // sim, then e=exp(sim-M) in place
__device__ float g_rS  [B*Q];             // 1/colsum
__device__ float g_smax[B*C];
__device__ float g_cdash[B*D];

// ---------------- helpers ----------------
__device__ __forceinline__ unsigned smem_u32(const void* p) {
    unsigned a;
    asm("{ .reg .u64 tmp; cvta.to.shared.u64 tmp, %1; cvt.u32.u64 %0, tmp; }" : "=r"(a) : "l"(p));
    return a;
}
__device__ __forceinline__ void ldm_x4(unsigned* r, const void* p) {
    unsigned a = smem_u32(p);
    asm volatile("ldmatrix.sync.aligned.m8n8.x4.shared.b16 {%0,%1,%2,%3}, [%4];"
        : "=r"(r[0]), "=r"(r[1]), "=r"(r[2]), "=r"(r[3]) : "r"(a));
}
__device__ __forceinline__ void ldm_x4t(unsigned* r, const void* p) {
    unsigned a = smem_u32(p);
    asm volatile("ldmatrix.sync.aligned.m8n8.x4.trans.shared.b16 {%0,%1,%2,%3}, [%4];"
        : "=r"(r[0]), "=r"(r[1]), "=r"(r[2]), "=r"(r[3]) : "r"(a));
}
__device__ __forceinline__ void mma_bf16(float* d, const unsigned* a, unsigned b0, unsigned b1) {
    asm volatile("mma.sync.aligned.m16n8k16.row.col.f32.bf16.bf16.f32 "
        "{%0,%1,%2,%3}, {%4,%5,%6,%7}, {%8,%9}, {%0,%1,%2,%3};"
        : "+f"(d[0]), "+f"(d[1]), "+f"(d[2]), "+f"(d[3])
        : "r"(a[0]), "r"(a[1]), "r"(a[2]), "r"(a[3]), "r"(b0), "r"(b1));
}
__device__ __forceinline__ void split2(float x0, float x1, unsigned& h, unsigned& l) {
    __nv_bfloat16 h0 = __float2bfloat16(x0), h1 = __float2bfloat16(x1);
    float r0 = x0 - __bfloat162float(h0), r1 = x1 - __bfloat162float(h1);
    __nv_bfloat16 l0 = __float2bfloat16(r0), l1 = __float2bfloat16(r1);
    unsigned short a0 = *(unsigned short*)&h0, a1 = *(unsigned short*)&h1;
    unsigned short b0 = *(unsigned short*)&l0, b1 = *(unsigned short*)&l1;
    h = (unsigned)a0 | ((unsigned)a1 << 16);
    l = (unsigned)b0 | ((unsigned)b1 << 16);
}

// ================= K1: sim GEMM =================
// tile 64(c) x 128(q), BK=32, 8 warps: wm=wid&1 (32 rows), wn=wid>>1 (32 cols)
__global__ __launch_bounds__(256, 2) void k_sim_mma(const float* __restrict__ cont,
                                                    const float* __restrict__ ques,
                                                    const float* __restrict__ SW) {
    __shared__ __nv_bfloat16 Ah[64][40], Al[64][40], Bh[128][40], Bl[128][40];
    __shared__ float sm_a[64], sm_bq[128], sm_rmax[4][64];
    const int cb = blockIdx.x, b = blockIdx.y;
    const int t = threadIdx.x, lane = t & 31, wid = t >> 5;
    const int wm = wid & 1, wn = wid >> 1;
    const int arow = t >> 2, acol = (t & 3) * 8;
    const int brow = t >> 1, bcol = (t & 1) * 16;

    const float* Ag = cont + ((size_t)(b * C + cb * 64 + arow)) * D + acol;
    const float* Bg = ques + ((size_t)(b * Q + brow)) * D + bcol;
    const float* w1 = SW;
    const float* w2 = SW + D;
    const float* w3 = SW + 2 * D;

    float acc[2][4][4];
    #pragma unroll
    for (int i = 0; i < 2; i++)
        #pragma unroll
        for (int j = 0; j < 4; j++)
            #pragma unroll
            for (int k = 0; k < 4; k++) acc[i][j][k] = 0.f;

    float a_part = 0.f, bq_part = 0.f;
    float4 ra[2], rb[4];
    #pragma unroll
    for (int j = 0; j < 2; j++) ra[j] = *(const float4*)(Ag + j * 4);
    #pragma unroll
    for (int j = 0; j < 4; j++) rb[j] = *(const float4*)(Bg + j * 4);

    for (int k0 = 0; k0 < D; k0 += 32) {
        if (k0) __syncthreads();
        #pragma unroll
        for (int j = 0; j < 2; j++) {
            int col = acol + j * 4;
            float4 w3v = *(const float4*)(w3 + k0 + col);
            float4 w1v = *(const float4*)(w1 + k0 + col);
            a_part += ra[j].x * w1v.x + ra[j].y * w1v.y + ra[j].z * w1v.z + ra[j].w * w1v.w;
            unsigned h0, l0, h1, l1;
            split2(ra[j].x * w3v.x, ra[j].y * w3v.y, h0, l0);
            split2(ra[j].z * w3v.z, ra[j].w * w3v.w, h1, l1);
            *(unsigned*)&Ah[arow][col]     = h0;  *(unsigned*)&Al[arow][col]     = l0;
            *(unsigned*)&Ah[arow][col + 2] = h1;  *(unsigned*)&Al[arow][col + 2] = l1;
        }
        #pragma unroll
        for (int j = 0; j < 4; j++) {
            int col = bcol + j * 4;
            float4 w2v = *(const float4*)(w2 + k0 + col);
            bq_part += rb[j].x * w2v.x + rb[j].y * w2v.y + rb[j].z * w2v.z + rb[j].w * w2v.w;
            unsigned h0, l0, h1, l1;
            split2(rb[j].x, rb[j].y, h0, l0);
            split2(rb[j].z, rb[j].w, h1, l1);
            *(unsigned*)&Bh[brow][col]     = h0;  *(unsigned*)&Bl[brow][col]     = l0;
            *(unsigned*)&Bh[brow][col + 2] = h1;  *(unsigned*)&Bl[brow][col + 2] = l1;
        }
        __syncthreads();
        if (k0 + 32 < D) {
            #pragma unroll
            for (int j = 0; j < 2; j++) ra[j] = *(const float4*)(Ag + k0 + 32 + j * 4);
            #pragma unroll
            for (int j = 0; j < 4; j++) rb[j] = *(const float4*)(Bg + k0 + 32 + j * 4);
        }
        #pragma unroll
        for (int kk = 0; kk < 2; kk++) {
            const int kb = kk * 16;
            unsigned afh[2][4], afl[2][4];
            #pragma unroll
            for (int mt = 0; mt < 2; mt++) {
                ldm_x4(afh[mt], &Ah[wm * 32 + mt * 16 + (lane & 15)][kb + (lane >> 4) * 8]);
                ldm_x4(afl[mt], &Al[wm * 32 + mt * 16 + (lane & 15)][kb + (lane >> 4) * 8]);
            }
            #pragma unroll
            for (int ng = 0; ng < 2; ng++) {
                unsigned bfh[4], bfl[4];
                ldm_x4(bfh, &Bh[wn * 32 + ng * 16 + (lane & 15)][kb + (lane >> 4) * 8]);
                ldm_x4(bfl, &Bl[wn * 32 + ng * 16 + (lane & 15)][kb + (lane >> 4) * 8]);
                #pragma unroll
                for (int h = 0; h < 2; h++) {
                    const int nt = ng * 2 + h;
                    #pragma unroll
                    for (int mt = 0; mt < 2; mt++) {
                        mma_bf16(acc[mt][nt], afh[mt], bfh[h], bfh[2 + h]);
                        mma_bf16(acc[mt][nt], afh[mt], bfl[h], bfl[2 + h]);
                        mma_bf16(acc[mt][nt], afl[mt], bfh[h], bfh[2 + h]);
                    }
                }
            }
        }
    }

    // bias dot reductions
    a_part += __shfl_xor_sync(0xffffffffu, a_part, 1);
    a_part += __shfl_xor_sync(0xffffffffu, a_part, 2);
    if ((t & 3) == 0) sm_a[arow] = a_part;
    bq_part += __shfl_xor_sync(0xffffffffu, bq_part, 1);
    if ((t & 1) == 0) sm_bq[brow] = bq_part;
    __syncthreads();

    // epilogue: bias add, store sim, row max
    #pragma unroll
    for (int mt = 0; mt < 2; mt++) {
        const int r0 = wm * 32 + mt * 16 + (lane >> 2);
        const float a0 = sm_a[r0], a1 = sm_a[r0 + 8];
        float m0 = -3.4e38f, m1 = -3.4e38f;
        #pragma unroll
        for (int nt = 0; nt < 4; nt++) {
            const int q0 = wn * 32 + nt * 8 + (lane & 3) * 2;
            const float bq0 = sm_bq[q0], bq1 = sm_bq[q0 + 1];
            float v00 = acc[mt][nt][0] + a0 + bq0;
            float v01 = acc[mt][nt][1] + a0 + bq1;
            float v10 = acc[mt][nt][2] + a1 + bq0;
            float v11 = acc[mt][nt][3] + a1 + bq1;
            *(float2*)(g_sim + ((size_t)(b * C + cb * 64 + r0)) * Q + q0)     = make_float2(v00, v01);
            *(float2*)(g_sim + ((size_t)(b * C + cb * 64 + r0 + 8)) * Q + q0) = make_float2(v10, v11);
            m0 = fmaxf(m0, fmaxf(v00, v01));
            m1 = fmaxf(m1, fmaxf(v10, v11));
        }
        m0 = fmaxf(m0, __shfl_xor_sync(0xffffffffu, m0, 1));
        m0 = fmaxf(m0, __shfl_xor_sync(0xffffffffu, m0, 2));
        m1 = fmaxf(m1, __shfl_xor_sync(0xffffffffu, m1, 1));
        m1 = fmaxf(m1, __shfl_xor_sync(0xffffffffu, m1, 2));
        if ((lane & 3) == 0) {
            sm_rmax[wn][r0]     = m0;
            sm_rmax[wn][r0 + 8] = m1;
        }
    }
    __syncthreads();
    if (t < 64)
        g_smax[b * C + cb * 64 + t] =
            fmaxf(fmaxf(sm_rmax[0][t], sm_rmax[1][t]), fmaxf(sm_rmax[2][t], sm_rmax[3][t]));
}

// ================= K2: column softmax stats, e in place =================
__global__ void k_colstats(const int* __restrict__ qmask) {
    const int b  = blockIdx.y;
    const int tx = threadIdx.x, ty = threadIdx.y;
    const int q  = blockIdx.x * 32 + tx;
    const int qm = qmask[b * Q + q];
    __shared__ float red[8][32];
    float m = -3.4e38f;
    for (int c = ty; c < C; c += 8) {
        float v = g_sim[((size_t)(b * C + c)) * Q + q];
        m = fmaxf(m, qm ? v : NEGBIG);
    }
    red[ty][tx] = m;
    __syncthreads();
    if (ty == 0) {
        #pragma unroll
        for (int k = 1; k < 8; k++) m = fmaxf(m, red[k][tx]);
        red[0][tx] = m;
    }
    __syncthreads();
    m = red[0][tx];
    __syncthreads();
    float s = 0.f;
    for (int c = ty; c < C; c += 8) {
        size_t idx = ((size_t)(b * C + c)) * Q + q;
        float v = g_sim[idx];
        float e = expf((qm ? v : NEGBIG) - m);
        g_sim[idx] = e;
        s += e;
    }
    red[ty][tx] = s;
    __syncthreads();
    if (ty == 0) {
        #pragma unroll
        for (int k = 1; k < 8; k++) s += red[k][tx];
        g_rS[b * Q + q] = 1.f / s;
    }
}

// ================= K3: c_dash (weights inline) =================
__global__ __launch_bounds__(256) void k_cdashW(const float* __restrict__ cont,
                                                const int* __restrict__ cmask) {
    __shared__ float red[256];
    __shared__ float w[512];
    const int b = blockIdx.y;
    const int t = threadIdx.x;
    float s0 = g_smax[b * C + t], s1 = g_smax[b * C + 256 + t];
    float ms0 = cmask[b * C + t] ? s0 : NEGBIG;
    float ms1 = cmask[b * C + 256 + t] ? s1 : NEGBIG;
    red[t] = fmaxf(ms0, ms1);
    __syncthreads();
    for (int o = 128; o; o >>= 1) {
        if (t < o) red[t] = fmaxf(red[t], red[t + o]);
        __syncthreads();
    }
    float M = red[0];
    __syncthreads();
    float e0 = expf(ms0 - M), e1 = expf(ms1 - M);
    red[t] = e0 + e1;
    __syncthreads();
    for (int o = 128; o; o >>= 1) {
        if (t < o) red[t] += red[t + o];
        __syncthreads();
    }
    float rS = 1.f / red[0];
    w[t] = e0 * rS;
    w[256 + t] = e1 * rS;
    __syncthreads();
    const int d = blockIdx.x * 256 + t;
    float acc = 0.f;
    const float* base = cont + (size_t)b * C * D + d;
    #pragma unroll 8
    for (int c = 0; c < C; c++) acc += w[c] * base[(size_t)c * D];
    g_cdash[b * D + d] = acc;
}

// ================= K4: c2q GEMM + full epilogue =================
// tile 64(c) x 128(d), BK=32 over Q; warps wm=wid&1 (32 rows), wn=wid>>1 (32 cols)
__global__ __launch_bounds__(256, 2) void k_c2q_mma(const float* __restrict__ cont,
                                                    const float* __restrict__ ques,
                                                    float* __restrict__ out) {
    __shared__ __nv_bfloat16 Ah[64][40], Al[64][40];
    __shared__ __nv_bfloat16 Bh[32][136], Bl[32][136];
    __shared__ float sm_rs[128], sm_cd[128];
    const int cb = blockIdx.x, dt = blockIdx.y, b = blockIdx.z;
    const int t = threadIdx.x, lane = t & 31, wid = t >> 5;
    const int wm = wid & 1, wn = wid >> 1;
    const int arow = t >> 2, acol = (t & 3) * 8;
    const int brow = t >> 3, bc0 = (t & 7) * 16;

    if (t < 128) {
        sm_rs[t] = g_rS[b * Q + t];
        sm_cd[t] = g_cdash[b * D + dt * 128 + t];
    }
    __syncthreads();

    const float* Ag = g_sim + ((size_t)(b * C + cb * 64 + arow)) * Q + acol;
    const float* Bg = ques + ((size_t)b * Q) * D + dt * 128;

    float acc[2][4][4];
    #pragma unroll
    for (int i = 0; i < 2; i++)
        #pragma unroll
        for (int j = 0; j < 4; j++)
            #pragma unroll
            for (int k = 0; k < 4; k++) acc[i][j][k] = 0.f;

    float4 ra[2], rb[4];
    #pragma unroll
    for (int j = 0; j < 2; j++) ra[j] = *(const float4*)(Ag + j * 4);
    #pragma unroll
    for (int j = 0; j < 4; j++) rb[j] = *(const float4*)(Bg + (size_t)brow * D + bc0 + j * 4);

    for (int k0 = 0; k0 < Q; k0 += 32) {
        if (k0) __syncthreads();
        #pragma unroll
        for (int j = 0; j < 2; j++) {
            int col = acol + j * 4;
            float r0 = sm_rs[k0 + col],     r1 = sm_rs[k0 + col + 1];
            float r2 = sm_rs[k0 + col + 2], r3 = sm_rs[k0 + col + 3];
            unsigned h0, l0, h1, l1;
            split2(ra[j].x * r0, ra[j].y * r1, h0, l0);
            split2(ra[j].z * r2, ra[j].w * r3, h1, l1);
            *(unsigned*)&Ah[arow][col]     = h0;  *(unsigned*)&Al[arow][col]     = l0;
            *(unsigned*)&Ah[arow][col + 2] = h1;  *(unsigned*)&Al[arow][col + 2] = l1;
        }
        #pragma unroll
        for (int j = 0; j < 4; j++) {
            int bcol = bc0 + j * 4;
            unsigned h0, l0, h1, l1;
            split2(rb[j].x, rb[j].y, h0, l0);
            split2(rb[j].z, rb[j].w, h1, l1);
            *(unsigned*)&Bh[brow][bcol]     = h0;  *(unsigned*)&Bl[brow][bcol]     = l0;
            *(unsigned*)&Bh[brow][bcol + 2] = h1;  *(unsigned*)&Bl[brow][bcol + 2] = l1;
        }
        __syncthreads();
        if (k0 + 32 < Q) {
            #pragma unroll
            for (int j = 0; j < 2; j++) ra[j] = *(const float4*)(Ag + k0 + 32 + j * 4);
            #pragma unroll
            for (int j = 0; j < 4; j++)
                rb[j] = *(const float4*)(Bg + (size_t)(k0 + 32 + brow) * D + bc0 + j * 4);
        }
        #pragma unroll
        for (int kk = 0; kk < 2; kk++) {
            const int kb = kk * 16;
            unsigned afh[2][4], afl[2][4];
            #pragma unroll
            for (int mt = 0; mt < 2; mt++) {
                ldm_x4(afh[mt], &Ah[wm * 32 + mt * 16 + (lane & 15)][kb + (lane >> 4) * 8]);
                ldm_x4(afl[mt], &Al[wm * 32 + mt * 16 + (lane & 15)][kb + (lane >> 4) * 8]);
            }
            #pragma unroll
            for (int ng = 0; ng < 2; ng++) {
                unsigned bfh[4], bfl[4];
                ldm_x4t(bfh, &Bh[kb + (lane & 15)][wn * 32 + ng * 16 + (lane >> 4) * 8]);
                ldm_x4t(bfl, &Bl[kb + (lane & 15)][wn * 32 + ng * 16 + (lane >> 4) * 8]);
                #pragma unroll
                for (int h = 0; h < 2; h++) {
                    const int nt = ng * 2 + h;
                    #pragma unroll
                    for (int mt = 0; mt < 2; mt++) {
                        mma_bf16(acc[mt][nt], afh[mt], bfh[2 * h], bfh[2 * h + 1]);
                        mma_bf16(acc[mt][nt], afh[mt], bfl[2 * h], bfl[2 * h + 1]);
                        mma_bf16(acc[mt][nt], afl[mt], bfh[2 * h], bfh[2 * h + 1]);
                    }
                }
            }
        }
    }

    // epilogue: out = concat[cont, c2q, cont*c2q, cont*c_dash]
    #pragma unroll
    for (int mt = 0; mt < 2; mt++) {
        const int rbase = cb * 64 + wm * 32 + mt * 16 + (lane >> 2);
        #pragma unroll
        for (int rr = 0; rr < 2; rr++) {
            const int c = rbase + rr * 8;
            const float* cr = cont + ((size_t)(b * C + c)) * D;
            float* ob = out + ((size_t)(b * C + c)) * OD;
            #pragma unroll
            for (int nt = 0; nt < 4; nt++) {
                const int dloc = wn * 32 + nt * 8 + (lane & 3) * 2;
                const int dd = dt * 128 + dloc;
                float2 ct = *(const float2*)(cr + dd);
                float2 cq = make_float2(acc[mt][nt][2 * rr], acc[mt][nt][2 * rr + 1]);
                float2 cd = *(const float2*)(sm_cd + dloc);
                float2 m1 = make_float2(ct.x * cq.x, ct.y * cq.y);
                float2 m2 = make_float2(ct.x * cd.x, ct.y * cd.y);
                *(float2*)(ob + dd)         = ct;
                *(float2*)(ob + D + dd)     = cq;
                *(float2*)(ob + 2 * D + dd) = m1;
                *(float2*)(ob + 3 * D + dd) = m2;
            }
        }
    }
}

// ---------------- launch ----------------
extern "C" void kernel_launch(void* const* d_in, const int* in_sizes, int n_in,
                              void* d_out, int out_size) {
    const float* cont  = (const float*)d_in[0];
    const int*   cmask = (const int*)d_in[1];
    const float* ques  = (const float*)d_in[2];
    const int*   qmask = (const int*)d_in[3];
    const float* SW    = (const float*)d_in[4];
    float* out = (float*)d_out;
    (void)in_sizes; (void)n_in; (void)out_size;

    {   dim3 g(C / 64, B);       k_sim_mma<<<g, 256>>>(cont, ques, SW); }
    {   dim3 g(Q / 32, B);       dim3 th(32, 8); k_colstats<<<g, th>>>(qmask); }
    {   dim3 g(D / 256, B);      k_cdashW<<<g, 256>>>(cont, cmask); }
    {   dim3 g(C / 64, D / 128, B); k_c2q_mma<<<g, 256>>>(cont, ques, out); }
}

// round 6
// speedup vs baseline: 1.4604x; 1.0699x over previous
#include <cuda_runtime.h>
#include <cuda_bf16.h>
#include <math.h>
#include <stdint.h>

#define B 32
#define C 512
#define Q 128
#define D 768
#define OD (4*D)
#define NEGBIG (-1e30f)

// ---------------- scratch ----------------
__device__ float g_sim [(size_t)B*C*Q];   // sim, then e=exp(sim-M) in place
__device__ float g_rS  [B*Q];             // 1/colsum
__device__ float g_smax[B*C];
__device__ float g_cdash[B*D];

// ---------------- helpers ----------------
__device__ __forceinline__ unsigned smem_u32(const void* p) {
    unsigned a;
    asm("{ .reg .u64 tmp; cvta.to.shared.u64 tmp, %1; cvt.u32.u64 %0, tmp; }" : "=r"(a) : "l"(p));
    return a;
}
__device__ __forceinline__ void ldm_x4(unsigned* r, const void* p) {
    unsigned a = smem_u32(p);
    asm volatile("ldmatrix.sync.aligned.m8n8.x4.shared.b16 {%0,%1,%2,%3}, [%4];"
        : "=r"(r[0]), "=r"(r[1]), "=r"(r[2]), "=r"(r[3]) : "r"(a));
}
__device__ __forceinline__ void ldm_x4t(unsigned* r, const void* p) {
    unsigned a = smem_u32(p);
    asm volatile("ldmatrix.sync.aligned.m8n8.x4.trans.shared.b16 {%0,%1,%2,%3}, [%4];"
        : "=r"(r[0]), "=r"(r[1]), "=r"(r[2]), "=r"(r[3]) : "r"(a));
}
__device__ __forceinline__ void mma_bf16(float* d, const unsigned* a, unsigned b0, unsigned b1) {
    asm volatile("mma.sync.aligned.m16n8k16.row.col.f32.bf16.bf16.f32 "
        "{%0,%1,%2,%3}, {%4,%5,%6,%7}, {%8,%9}, {%0,%1,%2,%3};"
        : "+f"(d[0]), "+f"(d[1]), "+f"(d[2]), "+f"(d[3])
        : "r"(a[0]), "r"(a[1]), "r"(a[2]), "r"(a[3]), "r"(b0), "r"(b1));
}
__device__ __forceinline__ void split2(float x0, float x1, unsigned& h, unsigned& l) {
    __nv_bfloat16 h0 = __float2bfloat16(x0), h1 = __float2bfloat16(x1);
    float r0 = x0 - __bfloat162float(h0), r1 = x1 - __bfloat162float(h1);
    __nv_bfloat16 l0 = __float2bfloat16(r0), l1 = __float2bfloat16(r1);
    unsigned short a0 = *(unsigned short*)&h0, a1 = *(unsigned short*)&h1;
    unsigned short b0 = *(unsigned short*)&l0, b1 = *(unsigned short*)&l1;
    h = (unsigned)a0 | ((unsigned)a1 << 16);
    l = (unsigned)b0 | ((unsigned)b1 << 16);
}

#define SSTRIDE 132

// ================= K1: sim GEMM =================
// tile 64(c) x 128(q), BK=32, 8 warps: wm=wid&1 (32 rows), wn=wid>>1 (32 cols)
__global__ __launch_bounds__(256, 2) void k_sim_mma(const float* __restrict__ cont,
                                                    const float* __restrict__ ques,
                                                    const float* __restrict__ SW) {
    __shared__ char buf[64 * SSTRIDE * 4];   // 33792 B: A/B tiles, then staging
    __shared__ float sm_a[64], sm_bq[128];
    __nv_bfloat16 (*Ah)[40] = (__nv_bfloat16 (*)[40])(buf);
    __nv_bfloat16 (*Al)[40] = (__nv_bfloat16 (*)[40])(buf + 5120);
    __nv_bfloat16 (*Bh)[40] = (__nv_bfloat16 (*)[40])(buf + 10240);
    __nv_bfloat16 (*Bl)[40] = (__nv_bfloat16 (*)[40])(buf + 20480);
    float* S = (float*)buf;

    const int cb = blockIdx.x, b = blockIdx.y;
    const int t = threadIdx.x, lane = t & 31, wid = t >> 5;
    const int wm = wid & 1, wn = wid >> 1;
    const int arow = t >> 2, acol = (t & 3) * 8;
    const int brow = t >> 1, bcol = (t & 1) * 16;

    const float* Ag = cont + ((size_t)(b * C + cb * 64 + arow)) * D + acol;
    const float* Bg = ques + ((size_t)(b * Q + brow)) * D + bcol;
    const float* w1 = SW;
    const float* w2 = SW + D;
    const float* w3 = SW + 2 * D;

    float acc[2][4][4];
    #pragma unroll
    for (int i = 0; i < 2; i++)
        #pragma unroll
        for (int j = 0; j < 4; j++)
            #pragma unroll
            for (int k = 0; k < 4; k++) acc[i][j][k] = 0.f;

    float a_part = 0.f, bq_part = 0.f;
    float4 ra[2], rb[4];
    #pragma unroll
    for (int j = 0; j < 2; j++) ra[j] = *(const float4*)(Ag + j * 4);
    #pragma unroll
    for (int j = 0; j < 4; j++) rb[j] = *(const float4*)(Bg + j * 4);

    for (int k0 = 0; k0 < D; k0 += 32) {
        if (k0) __syncthreads();
        #pragma unroll
        for (int j = 0; j < 2; j++) {
            int col = acol + j * 4;
            float4 w3v = *(const float4*)(w3 + k0 + col);
            float4 w1v = *(const float4*)(w1 + k0 + col);
            a_part += ra[j].x * w1v.x + ra[j].y * w1v.y + ra[j].z * w1v.z + ra[j].w * w1v.w;
            unsigned h0, l0, h1, l1;
            split2(ra[j].x * w3v.x, ra[j].y * w3v.y, h0, l0);
            split2(ra[j].z * w3v.z, ra[j].w * w3v.w, h1, l1);
            *(unsigned*)&Ah[arow][col]     = h0;  *(unsigned*)&Al[arow][col]     = l0;
            *(unsigned*)&Ah[arow][col + 2] = h1;  *(unsigned*)&Al[arow][col + 2] = l1;
        }
        #pragma unroll
        for (int j = 0; j < 4; j++) {
            int col = bcol + j * 4;
            float4 w2v = *(const float4*)(w2 + k0 + col);
            bq_part += rb[j].x * w2v.x + rb[j].y * w2v.y + rb[j].z * w2v.z + rb[j].w * w2v.w;
            unsigned h0, l0, h1, l1;
            split2(rb[j].x, rb[j].y, h0, l0);
            split2(rb[j].z, rb[j].w, h1, l1);
            *(unsigned*)&Bh[brow][col]     = h0;  *(unsigned*)&Bl[brow][col]     = l0;
            *(unsigned*)&Bh[brow][col + 2] = h1;  *(unsigned*)&Bl[brow][col + 2] = l1;
        }
        __syncthreads();
        if (k0 + 32 < D) {
            #pragma unroll
            for (int j = 0; j < 2; j++) ra[j] = *(const float4*)(Ag + k0 + 32 + j * 4);
            #pragma unroll
            for (int j = 0; j < 4; j++) rb[j] = *(const float4*)(Bg + k0 + 32 + j * 4);
        }
        #pragma unroll
        for (int kk = 0; kk < 2; kk++) {
            const int kb = kk * 16;
            unsigned afh[2][4], afl[2][4];
            #pragma unroll
            for (int mt = 0; mt < 2; mt++) {
                ldm_x4(afh[mt], &Ah[wm * 32 + mt * 16 + (lane & 15)][kb + (lane >> 4) * 8]);
                ldm_x4(afl[mt], &Al[wm * 32 + mt * 16 + (lane & 15)][kb + (lane >> 4) * 8]);
            }
            #pragma unroll
            for (int ng = 0; ng < 2; ng++) {
                unsigned bfh[4], bfl[4];
                ldm_x4(bfh, &Bh[wn * 32 + ng * 16 + (lane & 15)][kb + (lane >> 4) * 8]);
                ldm_x4(bfl, &Bl[wn * 32 + ng * 16 + (lane & 15)][kb + (lane >> 4) * 8]);
                #pragma unroll
                for (int h = 0; h < 2; h++) {
                    const int nt = ng * 2 + h;
                    #pragma unroll
                    for (int mt = 0; mt < 2; mt++) {
                        mma_bf16(acc[mt][nt], afh[mt], bfh[h], bfh[2 + h]);
                        mma_bf16(acc[mt][nt], afh[mt], bfl[h], bfl[2 + h]);
                        mma_bf16(acc[mt][nt], afl[mt], bfh[h], bfh[2 + h]);
                    }
                }
            }
        }
    }

    // bias dot reductions
    a_part += __shfl_xor_sync(0xffffffffu, a_part, 1);
    a_part += __shfl_xor_sync(0xffffffffu, a_part, 2);
    if ((t & 3) == 0) sm_a[arow] = a_part;
    bq_part += __shfl_xor_sync(0xffffffffu, bq_part, 1);
    if ((t & 1) == 0) sm_bq[brow] = bq_part;
    __syncthreads();   // also: last compute done before staging overwrites A/B smem

    // stage accumulators into S[64][SSTRIDE]
    #pragma unroll
    for (int mt = 0; mt < 2; mt++) {
        const int r0 = wm * 32 + mt * 16 + (lane >> 2);
        #pragma unroll
        for (int nt = 0; nt < 4; nt++) {
            const int q0 = wn * 32 + nt * 8 + (lane & 3) * 2;
            *(float2*)&S[r0 * SSTRIDE + q0]       = make_float2(acc[mt][nt][0], acc[mt][nt][1]);
            *(float2*)&S[(r0 + 8) * SSTRIDE + q0] = make_float2(acc[mt][nt][2], acc[mt][nt][3]);
        }
    }
    __syncthreads();

    // coalesced writeback + exact row max
    float4 bq4 = *(const float4*)&sm_bq[lane * 4];
    #pragma unroll
    for (int r = 0; r < 8; r++) {
        const int row = wid * 8 + r;
        float4 v = *(const float4*)&S[row * SSTRIDE + lane * 4];
        float a = sm_a[row];
        v.x += a + bq4.x; v.y += a + bq4.y; v.z += a + bq4.z; v.w += a + bq4.w;
        float m = fmaxf(fmaxf(v.x, v.y), fmaxf(v.z, v.w));
        #pragma unroll
        for (int o = 16; o; o >>= 1) m = fmaxf(m, __shfl_xor_sync(0xffffffffu, m, o));
        *(float4*)(g_sim + ((size_t)(b * C + cb * 64 + row)) * Q + lane * 4) = v;
        if (lane == 0) g_smax[b * C + cb * 64 + row] = m;
    }
}

// ================= K2: column softmax stats, e in place =================
__global__ void k_colstats(const int* __restrict__ qmask) {
    const int b  = blockIdx.y;
    const int tx = threadIdx.x, ty = threadIdx.y;
    const int q  = blockIdx.x * 32 + tx;
    const int qm = qmask[b * Q + q];
    __shared__ float red[8][32];
    float m = -3.4e38f;
    for (int c = ty; c < C; c += 8) {
        float v = g_sim[((size_t)(b * C + c)) * Q + q];
        m = fmaxf(m, qm ? v : NEGBIG);
    }
    red[ty][tx] = m;
    __syncthreads();
    if (ty == 0) {
        #pragma unroll
        for (int k = 1; k < 8; k++) m = fmaxf(m, red[k][tx]);
        red[0][tx] = m;
    }
    __syncthreads();
    m = red[0][tx];
    __syncthreads();
    float s = 0.f;
    for (int c = ty; c < C; c += 8) {
        size_t idx = ((size_t)(b * C + c)) * Q + q;
        float v = g_sim[idx];
        float e = expf((qm ? v : NEGBIG) - m);
        g_sim[idx] = e;
        s += e;
    }
    red[ty][tx] = s;
    __syncthreads();
    if (ty == 0) {
        #pragma unroll
        for (int k = 1; k < 8; k++) s += red[k][tx];
        g_rS[b * Q + q] = 1.f / s;
    }
}

// ================= K3: c_dash (weights inline) =================
__global__ __launch_bounds__(256) void k_cdashW(const float* __restrict__ cont,
                                                const int* __restrict__ cmask) {
    __shared__ float red[256];
    __shared__ float w[512];
    const int b = blockIdx.y;
    const int t = threadIdx.x;
    float s0 = g_smax[b * C + t], s1 = g_smax[b * C + 256 + t];
    float ms0 = cmask[b * C + t] ? s0 : NEGBIG;
    float ms1 = cmask[b * C + 256 + t] ? s1 : NEGBIG;
    red[t] = fmaxf(ms0, ms1);
    __syncthreads();
    for (int o = 128; o; o >>= 1) {
        if (t < o) red[t] = fmaxf(red[t], red[t + o]);
        __syncthreads();
    }
    float M = red[0];
    __syncthreads();
    float e0 = expf(ms0 - M), e1 = expf(ms1 - M);
    red[t] = e0 + e1;
    __syncthreads();
    for (int o = 128; o; o >>= 1) {
        if (t < o) red[t] += red[t + o];
        __syncthreads();
    }
    float rS = 1.f / red[0];
    w[t] = e0 * rS;
    w[256 + t] = e1 * rS;
    __syncthreads();
    const int d = blockIdx.x * 256 + t;
    float acc = 0.f;
    const float* base = cont + (size_t)b * C * D + d;
    #pragma unroll 8
    for (int c = 0; c < C; c++) acc += w[c] * base[(size_t)c * D];
    g_cdash[b * D + d] = acc;
}

// ================= K4: c2q GEMM + full epilogue =================
// tile 64(c) x 128(d), BK=32 over Q
__global__ __launch_bounds__(256, 2) void k_c2q_mma(const float* __restrict__ cont,
                                                    const float* __restrict__ ques,
                                                    float* __restrict__ out) {
    __shared__ char buf[64 * SSTRIDE * 4];   // A/B tiles, then staging
    __shared__ float sm_rs[128], sm_cd[128];
    __nv_bfloat16 (*Ah)[40]  = (__nv_bfloat16 (*)[40])(buf);
    __nv_bfloat16 (*Al)[40]  = (__nv_bfloat16 (*)[40])(buf + 5120);
    __nv_bfloat16 (*Bh)[136] = (__nv_bfloat16 (*)[136])(buf + 10240);
    __nv_bfloat16 (*Bl)[136] = (__nv_bfloat16 (*)[136])(buf + 10240 + 8704);
    float* S = (float*)buf;

    const int cb = blockIdx.x, dt = blockIdx.y, b = blockIdx.z;
    const int t = threadIdx.x, lane = t & 31, wid = t >> 5;
    const int wm = wid & 1, wn = wid >> 1;
    const int arow = t >> 2, acol = (t & 3) * 8;
    const int brow = t >> 3, bc0 = (t & 7) * 16;

    if (t < 128) {
        sm_rs[t] = g_rS[b * Q + t];
        sm_cd[t] = g_cdash[b * D + dt * 128 + t];
    }
    __syncthreads();

    const float* Ag = g_sim + ((size_t)(b * C + cb * 64 + arow)) * Q + acol;
    const float* Bg = ques + ((size_t)b * Q) * D + dt * 128;

    float acc[2][4][4];
    #pragma unroll
    for (int i = 0; i < 2; i++)
        #pragma unroll
        for (int j = 0; j < 4; j++)
            #pragma unroll
            for (int k = 0; k < 4; k++) acc[i][j][k] = 0.f;

    float4 ra[2], rb[4];
    #pragma unroll
    for (int j = 0; j < 2; j++) ra[j] = *(const float4*)(Ag + j * 4);
    #pragma unroll
    for (int j = 0; j < 4; j++) rb[j] = *(const float4*)(Bg + (size_t)brow * D + bc0 + j * 4);

    for (int k0 = 0; k0 < Q; k0 += 32) {
        if (k0) __syncthreads();
        #pragma unroll
        for (int j = 0; j < 2; j++) {
            int col = acol + j * 4;
            float r0 = sm_rs[k0 + col],     r1 = sm_rs[k0 + col + 1];
            float r2 = sm_rs[k0 + col + 2], r3 = sm_rs[k0 + col + 3];
            unsigned h0, l0, h1, l1;
            split2(ra[j].x * r0, ra[j].y * r1, h0, l0);
            split2(ra[j].z * r2, ra[j].w * r3, h1, l1);
            *(unsigned*)&Ah[arow][col]     = h0;  *(unsigned*)&Al[arow][col]     = l0;
            *(unsigned*)&Ah[arow][col + 2] = h1;  *(unsigned*)&Al[arow][col + 2] = l1;
        }
        #pragma unroll
        for (int j = 0; j < 4; j++) {
            int bcol = bc0 + j * 4;
            unsigned h0, l0, h1, l1;
            split2(rb[j].x, rb[j].y, h0, l0);
            split2(rb[j].z, rb[j].w, h1, l1);
            *(unsigned*)&Bh[brow][bcol]     = h0;  *(unsigned*)&Bl[brow][bcol]     = l0;
            *(unsigned*)&Bh[brow][bcol + 2] = h1;  *(unsigned*)&Bl[brow][bcol + 2] = l1;
        }
        __syncthreads();
        if (k0 + 32 < Q) {
            #pragma unroll
            for (int j = 0; j < 2; j++) ra[j] = *(const float4*)(Ag + k0 + 32 + j * 4);
            #pragma unroll
            for (int j = 0; j < 4; j++)
                rb[j] = *(const float4*)(Bg + (size_t)(k0 + 32 + brow) * D + bc0 + j * 4);
        }
        #pragma unroll
        for (int kk = 0; kk < 2; kk++) {
            const int kb = kk * 16;
            unsigned afh[2][4], afl[2][4];
            #pragma unroll
            for (int mt = 0; mt < 2; mt++) {
                ldm_x4(afh[mt], &Ah[wm * 32 + mt * 16 + (lane & 15)][kb + (lane >> 4) * 8]);
                ldm_x4(afl[mt], &Al[wm * 32 + mt * 16 + (lane & 15)][kb + (lane >> 4) * 8]);
            }
            #pragma unroll
            for (int ng = 0; ng < 2; ng++) {
                unsigned bfh[4], bfl[4];
                ldm_x4t(bfh, &Bh[kb + (lane & 15)][wn * 32 + ng * 16 + (lane >> 4) * 8]);
                ldm_x4t(bfl, &Bl[kb + (lane & 15)][wn * 32 + ng * 16 + (lane >> 4) * 8]);
                #pragma unroll
                for (int h = 0; h < 2; h++) {
                    const int nt = ng * 2 + h;
                    #pragma unroll
                    for (int mt = 0; mt < 2; mt++) {
                        mma_bf16(acc[mt][nt], afh[mt], bfh[2 * h], bfh[2 * h + 1]);
                        mma_bf16(acc[mt][nt], afh[mt], bfl[2 * h], bfl[2 * h + 1]);
                        mma_bf16(acc[mt][nt], afl[mt], bfh[2 * h], bfh[2 * h + 1]);
                    }
                }
            }
        }
    }
    __syncthreads();   // last compute done; safe to overwrite A/B smem

    // stage accumulators into S[64][SSTRIDE]
    #pragma unroll
    for (int mt = 0; mt < 2; mt++) {
        const int r0 = wm * 32 + mt * 16 + (lane >> 2);
        #pragma unroll
        for (int nt = 0; nt < 4; nt++) {
            const int d0 = wn * 32 + nt * 8 + (lane & 3) * 2;
            *(float2*)&S[r0 * SSTRIDE + d0]       = make_float2(acc[mt][nt][0], acc[mt][nt][1]);
            *(float2*)&S[(r0 + 8) * SSTRIDE + d0] = make_float2(acc[mt][nt][2], acc[mt][nt][3]);
        }
    }
    __syncthreads();

    // coalesced epilogue: out = concat[cont, c2q, cont*c2q, cont*c_dash]
    float4 cd = *(const float4*)&sm_cd[lane * 4];
    #pragma unroll
    for (int r = 0; r < 8; r++) {
        const int row = wid * 8 + r;
        const int c = cb * 64 + row;
        float4 cq = *(const float4*)&S[row * SSTRIDE + lane * 4];
        float4 ct = *(const float4*)(cont + ((size_t)(b * C + c)) * D + dt * 128 + lane * 4);
        float4 m1 = make_float4(ct.x * cq.x, ct.y * cq.y, ct.z * cq.z, ct.w * cq.w);
        float4 m2 = make_float4(ct.x * cd.x, ct.y * cd.y, ct.z * cd.z, ct.w * cd.w);
        float* ob = out + ((size_t)(b * C + c)) * OD + dt * 128 + lane * 4;
        *(float4*)(ob)         = ct;
        *(float4*)(ob + D)     = cq;
        *(float4*)(ob + 2 * D) = m1;
        *(float4*)(ob + 3 * D) = m2;
    }
}

// ---------------- launch ----------------
extern "C" void kernel_launch(void* const* d_in, const int* in_sizes, int n_in,
                              void* d_out, int out_size) {
    const float* cont  = (const float*)d_in[0];
    const int*   cmask = (const int*)d_in[1];
    const float* ques  = (const float*)d_in[2];
    const int*   qmask = (const int*)d_in[3];
    const float* SW    = (const float*)d_in[4];
    float* out = (float*)d_out;
    (void)in_sizes; (void)n_in; (void)out_size;

    {   dim3 g(C / 64, B);       k_sim_mma<<<g, 256>>>(cont, ques, SW); }
    {   dim3 g(Q / 32, B);       dim3 th(32, 8); k_colstats<<<g, th>>>(qmask); }
    {   dim3 g(D / 256, B);      k_cdashW<<<g, 256>>>(cont, cmask); }
    {   dim3 g(C / 64, D / 128, B); k_c2q_mma<<<g, 256>>>(cont, ques, out); }
}